// round 11
// baseline (speedup 1.0000x reference)
#include <cuda_runtime.h>
#include <cuda_fp16.h>
#include <cstdint>

#define D_DIM 256
#define NTOK  65536
#define KCODE 4096
#define SCALE 4.0f          // z,e scaled by 4 -> dot scaled by 16 -> score = esqp - 0.125*acc

// ---------------- scratch globals ----------------
__device__ float  g_esqp[KCODE];        // esq + 2048 (fp32)
__device__ int    g_counts[KCODE];
__device__ float  g_partials[NTOK / 8];
__device__ __align__(16) uint8_t g_E8[KCODE * D_DIM];   // e4m3, scale 4
__device__ __align__(16) uint8_t g_Z8[NTOK * D_DIM];    // e4m3, scale 4
__device__ __align__(16) uint32_t g_topk[NTOK * 8];
__device__ int    g_done;

// SMEM: A 32KB | B0 32KB | B1 32KB | tops 8KB
#define SM_A    0
#define SM_B0   32768
#define SM_B1   65536
#define SM_TOP  98304
#define SMEM_TOTAL 106496

static __device__ __forceinline__ uint32_t smem_u32(const void* p) {
    uint32_t a;
    asm("{ .reg .u64 t; cvta.to.shared.u64 t, %1; cvt.u32.u64 %0, t; }" : "=r"(a) : "l"(p));
    return a;
}
static __device__ __forceinline__ void ldsm4(uint32_t* r, uint32_t addr) {
    asm volatile("ldmatrix.sync.aligned.m8n8.x4.shared.b16 {%0,%1,%2,%3}, [%4];"
                 : "=r"(r[0]), "=r"(r[1]), "=r"(r[2]), "=r"(r[3]) : "r"(addr));
}
// fp8 e4m3 x e4m3 -> f16 accumulate, m16n8k32
static __device__ __forceinline__ void qmma16832_f16(uint32_t& c0, uint32_t& c1,
                                                     const uint32_t* a, uint32_t b0, uint32_t b1) {
    asm volatile("mma.sync.aligned.m16n8k32.row.col.f16.e4m3.e4m3.f16 "
                 "{%0,%1}, {%2,%3,%4,%5}, {%6,%7}, {%0,%1};"
                 : "+r"(c0), "+r"(c1)
                 : "r"(a[0]), "r"(a[1]), "r"(a[2]), "r"(a[3]), "r"(b0), "r"(b1));
}
static __device__ __forceinline__ void cpasync16(uint32_t sa, const void* ga) {
    asm volatile("cp.async.cg.shared.global [%0], [%1], 16;" :: "r"(sa), "l"(ga));
}
// pack two floats into two e4m3 (lo in low byte)
static __device__ __forceinline__ uint16_t cvt2_e4m3(float lo, float hi) {
    uint16_t r;
    asm("cvt.rn.satfinite.e4m3x2.f32 %0, %1, %2;" : "=h"(r) : "f"(hi), "f"(lo));
    return r;
}
// sorted ascending depth-8 insert (branchy fast path)
static __device__ __forceinline__ void ins8u(uint32_t k, uint32_t* t) {
    if (k < t[7]) {
        uint32_t m;
        m = min(t[6], k); t[7] = max(t[6], k);
        k = m; m = min(t[5], k); t[6] = max(t[5], k);
        k = m; m = min(t[4], k); t[5] = max(t[4], k);
        k = m; m = min(t[3], k); t[4] = max(t[3], k);
        k = m; m = min(t[2], k); t[3] = max(t[2], k);
        k = m; m = min(t[1], k); t[2] = max(t[1], k);
        k = m; m = min(t[0], k); t[1] = max(t[0], k); t[0] = m;
    }
}

// ---------------- kernel 1: prep E (esqp, fp8 convert, zero counts) ----------------
__global__ void prep_e_kernel(const float* __restrict__ E) {
    int warp = threadIdx.x >> 5, lane = threadIdx.x & 31;
    int k = blockIdx.x * 8 + warp;
    const float* row = E + (size_t)k * D_DIM;
    float4 a = *reinterpret_cast<const float4*>(row + lane * 8);
    float4 b = *reinterpret_cast<const float4*>(row + lane * 8 + 4);
    float s = a.x * a.x + a.y * a.y + a.z * a.z + a.w * a.w
            + b.x * b.x + b.y * b.y + b.z * b.z + b.w * b.w;
#pragma unroll
    for (int o = 16; o > 0; o >>= 1) s += __shfl_xor_sync(0xffffffffu, s, o);
    uint16_t q[4];
    q[0] = cvt2_e4m3(a.x * SCALE, a.y * SCALE);
    q[1] = cvt2_e4m3(a.z * SCALE, a.w * SCALE);
    q[2] = cvt2_e4m3(b.x * SCALE, b.y * SCALE);
    q[3] = cvt2_e4m3(b.z * SCALE, b.w * SCALE);
    *reinterpret_cast<uint2*>(g_E8 + (size_t)k * D_DIM + lane * 8) = *reinterpret_cast<uint2*>(q);
    if (lane == 0) g_esqp[k] = s + 2048.0f;
    if (blockIdx.x < 16) g_counts[blockIdx.x * 256 + threadIdx.x] = 0;
}

// ---------------- kernel 2: Z -> fp8 ----------------
__global__ void quant_z_kernel(const float* __restrict__ Z) {
    int warp = threadIdx.x >> 5, lane = threadIdx.x & 31;
    int n = blockIdx.x * 8 + warp;
    const float* row = Z + (size_t)n * D_DIM;
    float4 a = *reinterpret_cast<const float4*>(row + lane * 8);
    float4 b = *reinterpret_cast<const float4*>(row + lane * 8 + 4);
    uint16_t q[4];
    q[0] = cvt2_e4m3(a.x * SCALE, a.y * SCALE);
    q[1] = cvt2_e4m3(a.z * SCALE, a.w * SCALE);
    q[2] = cvt2_e4m3(b.x * SCALE, b.y * SCALE);
    q[3] = cvt2_e4m3(b.z * SCALE, b.w * SCALE);
    *reinterpret_cast<uint2*>(g_Z8 + (size_t)n * D_DIM + lane * 8) = *reinterpret_cast<uint2*>(q);
}

__global__ void dummy_kernel() {}

// ---------------- kernel 3: fp8 QMMA(f16 acc) GEMM + interleaved top-8 ----------------
// tile = 128 rows x 256 bytes = 32KB; 2048 16B chunks over 256 threads
static __device__ __forceinline__ void load_tile_fp8(uint32_t dst, const uint8_t* gsrc, int tid) {
#pragma unroll
    for (int i = 0; i < 8; i++) {
        int c = tid + i * 256;
        int row = c >> 4, ch = c & 15;
        uint32_t sa = dst + row * 256 + (uint32_t)((ch ^ (row & 7)) << 4);
        cpasync16(sa, gsrc + row * 256 + ch * 16);
    }
}

// one tile: 8 k-steps (k32 each), MMAs into cur[], interleaved depth-8 epilogue of prev[]
static __device__ __forceinline__ void tile_body(
    int nt, bool hasPrev, uint32_t sb, int tid, int lane, int wm, int wn,
    uint32_t cur[2][8][2], uint32_t prev[2][8][2], uint32_t T[4][8])
{
    if (nt < 31) asm volatile("cp.async.wait_group 1;" ::: "memory");
    else         asm volatile("cp.async.wait_group 0;" ::: "memory");
    __syncthreads();
    const uint32_t Bb = sb + ((nt & 1) ? SM_B1 : SM_B0);

    float2 e2[8];
    const int kbase = (nt - 1) * 128 + wn * 64 + (lane & 3) * 2;
    if (hasPrev) {
#pragma unroll
        for (int nj = 0; nj < 8; nj++)
            e2[nj] = *reinterpret_cast<const float2*>(g_esqp + kbase + nj * 8);
    }

#pragma unroll
    for (int mi = 0; mi < 2; mi++)
#pragma unroll
        for (int nj = 0; nj < 8; nj++) { cur[mi][nj][0] = 0u; cur[mi][nj][1] = 0u; }

#pragma unroll
    for (int ks = 0; ks < 8; ks++) {
        uint32_t a[2][4], b[4][4];
#pragma unroll
        for (int mi = 0; mi < 2; mi++) {
            int ar = wm * 32 + mi * 16 + (lane & 15);
            int ch = ks * 2 + (lane >> 4);
            ldsm4(a[mi], sb + SM_A + ar * 256 + ((ch ^ (ar & 7)) << 4));
        }
#pragma unroll
        for (int g = 0; g < 4; g++) {
            int br = wn * 64 + g * 16 + (lane & 7) + ((lane >> 4) & 1) * 8;
            int ch = ks * 2 + ((lane >> 3) & 1);
            ldsm4(b[g], Bb + br * 256 + ((ch ^ (br & 7)) << 4));
        }
#pragma unroll
        for (int mi = 0; mi < 2; mi++)
#pragma unroll
            for (int g = 0; g < 4; g++) {
                qmma16832_f16(cur[mi][2 * g][0],     cur[mi][2 * g][1],     a[mi], b[g][0], b[g][1]);
                qmma16832_f16(cur[mi][2 * g + 1][0], cur[mi][2 * g + 1][1], a[mi], b[g][2], b[g][3]);
            }

        // interleaved epilogue of tile nt-1: 4 half2 chunks per k-step
        if (hasPrev) {
            const int mi = ks & 1;
            const int njb = (ks >> 1) * 2;
#pragma unroll
            for (int dj = 0; dj < 2; dj++) {
                const int nj = njb + dj;
                const int kb = kbase + nj * 8;
#pragma unroll
                for (int h = 0; h < 2; h++) {
                    const int s = mi * 2 + h;
                    float2 d = __half22float2(*reinterpret_cast<__half2*>(&prev[mi][nj][h]));
                    float v0 = fmaf(-0.125f, d.x, e2[nj].x);
                    float v1 = fmaf(-0.125f, d.y, e2[nj].y);
                    uint32_t k0 = (__float_as_uint(v0) & 0xFFFFF000u) | (uint32_t)kb;
                    uint32_t k1 = (__float_as_uint(v1) & 0xFFFFF000u) | (uint32_t)(kb + 1);
                    ins8u(k0, T[s]);
                    ins8u(k1, T[s]);
                }
            }
        }
    }
    __syncthreads();
    if (nt + 2 < 32) {
        load_tile_fp8(sb + ((nt & 1) ? SM_B1 : SM_B0), g_E8 + (size_t)(nt + 2) * 128 * D_DIM, tid);
        asm volatile("cp.async.commit_group;" ::: "memory");
    }
}

static __device__ __forceinline__ void tail_epilogue(
    int lane, int wn, uint32_t prev[2][8][2], uint32_t T[4][8])
{
    const int kbase = 31 * 128 + wn * 64 + (lane & 3) * 2;
#pragma unroll
    for (int nj = 0; nj < 8; nj++) {
        const int kb = kbase + nj * 8;
        float2 e2 = *reinterpret_cast<const float2*>(g_esqp + kb);
#pragma unroll
        for (int mi = 0; mi < 2; mi++)
#pragma unroll
            for (int h = 0; h < 2; h++) {
                const int s = mi * 2 + h;
                float2 d = __half22float2(*reinterpret_cast<__half2*>(&prev[mi][nj][h]));
                float v0 = fmaf(-0.125f, d.x, e2.x);
                float v1 = fmaf(-0.125f, d.y, e2.y);
                uint32_t k0 = (__float_as_uint(v0) & 0xFFFFF000u) | (uint32_t)kb;
                uint32_t k1 = (__float_as_uint(v1) & 0xFFFFF000u) | (uint32_t)(kb + 1);
                ins8u(k0, T[s]);
                ins8u(k1, T[s]);
            }
    }
}

__global__ __launch_bounds__(256, 1)
void approx_kernel() {
    extern __shared__ char smem[];
    const uint32_t sb = smem_u32(smem);
    const int tid = threadIdx.x;
    const int lane = tid & 31;
    const int wid = tid >> 5;
    const int wm = wid & 3;      // M warp (rows wm*32)
    const int wn = wid >> 2;     // N warp (cols wn*64)
    const int m0 = blockIdx.x * 128;

    load_tile_fp8(sb + SM_A, g_Z8 + (size_t)m0 * D_DIM, tid);
    load_tile_fp8(sb + SM_B0, g_E8, tid);
    asm volatile("cp.async.commit_group;" ::: "memory");
    load_tile_fp8(sb + SM_B1, g_E8 + 128 * D_DIM, tid);
    asm volatile("cp.async.commit_group;" ::: "memory");

    uint32_t T[4][8];
#pragma unroll
    for (int s = 0; s < 4; s++)
#pragma unroll
        for (int j = 0; j < 8; j++) T[s][j] = 0xFFFFFFFFu;

    uint32_t accA[2][8][2], accB[2][8][2];

#pragma unroll 1
    for (int p = 0; p < 16; p++) {
        tile_body(2 * p,     (p > 0), sb, tid, lane, wm, wn, accA, accB, T);
        tile_body(2 * p + 1, true,    sb, tid, lane, wm, wn, accB, accA, T);
    }
    tail_epilogue(lane, wn, accB, T);

    // quad merge: lanes l^1, l^2 share token rows
#pragma unroll
    for (int off = 1; off <= 2; off <<= 1) {
#pragma unroll
        for (int s = 0; s < 4; s++) {
            uint32_t o[8];
#pragma unroll
            for (int j = 0; j < 8; j++) o[j] = __shfl_xor_sync(0xffffffffu, T[s][j], off);
#pragma unroll
            for (int j = 0; j < 8; j++) ins8u(o[j], T[s]);
        }
    }

    uint32_t* smk = reinterpret_cast<uint32_t*>(smem + SM_TOP);
    if ((lane & 3) == 0) {
#pragma unroll
        for (int s = 0; s < 4; s++) {
            int r = wm * 32 + (s >> 1) * 16 + (s & 1) * 8 + (lane >> 2);
            uint32_t* dst = smk + (r * 2 + wn) * 8;
#pragma unroll
            for (int j = 0; j < 8; j++) dst[j] = T[s][j];
        }
    }
    __syncthreads();
    if (tid < 128) {
        uint32_t F[8];
        uint4 A0 = *reinterpret_cast<uint4*>(smk + (tid * 2) * 8);
        uint4 A1 = *reinterpret_cast<uint4*>(smk + (tid * 2) * 8 + 4);
        F[0] = A0.x; F[1] = A0.y; F[2] = A0.z; F[3] = A0.w;
        F[4] = A1.x; F[5] = A1.y; F[6] = A1.z; F[7] = A1.w;
        uint4 B0 = *reinterpret_cast<uint4*>(smk + (tid * 2 + 1) * 8);
        uint4 B1 = *reinterpret_cast<uint4*>(smk + (tid * 2 + 1) * 8 + 4);
        ins8u(B0.x, F); ins8u(B0.y, F); ins8u(B0.z, F); ins8u(B0.w, F);
        ins8u(B1.x, F); ins8u(B1.y, F); ins8u(B1.z, F); ins8u(B1.w, F);
        uint32_t* dst = &g_topk[(size_t)(m0 + tid) * 8];
        *reinterpret_cast<uint4*>(dst)     = make_uint4(F[0], F[1], F[2], F[3]);
        *reinterpret_cast<uint4*>(dst + 4) = make_uint4(F[4], F[5], F[6], F[7]);
    }
}

// ---------------- kernel 4: exact rescore(8) + gather + loss + hist + finalize ----------------
__global__ void rescue_kernel(const float* __restrict__ Z, const float* __restrict__ E,
                              float* __restrict__ zq_out, float* __restrict__ out_idx_f,
                              float* __restrict__ out_scalars, int N, int K) {
    const int warp = threadIdx.x >> 5;
    const int lane = threadIdx.x & 31;
    const int token = blockIdx.x * 8 + warp;

    const float* zr = Z + (size_t)token * D_DIM;
    float4 z0 = *reinterpret_cast<const float4*>(zr + lane * 8);
    float4 z1 = *reinterpret_cast<const float4*>(zr + lane * 8 + 4);

    const uint32_t* tk = &g_topk[(size_t)token * 8];
    int ks[8]; float dots[8];
#pragma unroll
    for (int j = 0; j < 8; j++) {
        int k = (int)(tk[j] & 4095u);
        ks[j] = k;
        const float* er = E + (size_t)k * D_DIM;
        float4 e0 = *reinterpret_cast<const float4*>(er + lane * 8);
        float4 e1 = *reinterpret_cast<const float4*>(er + lane * 8 + 4);
        dots[j] = z0.x * e0.x + z0.y * e0.y + z0.z * e0.z + z0.w * e0.w
                + z1.x * e1.x + z1.y * e1.y + z1.z * e1.z + z1.w * e1.w;
    }
#pragma unroll
    for (int o = 16; o > 0; o >>= 1)
#pragma unroll
        for (int j = 0; j < 8; j++) dots[j] += __shfl_xor_sync(0xffffffffu, dots[j], o);

    float bv = 3.4e38f; int bk = 0x7FFFFFFF;
#pragma unroll
    for (int j = 0; j < 8; j++) {
        float v = g_esqp[ks[j]] - 2048.0f - 2.0f * dots[j];
        if (v < bv || (v == bv && ks[j] < bk)) { bv = v; bk = ks[j]; }
    }

    const float* er = E + (size_t)bk * D_DIM;
    float* orow = zq_out + (size_t)token * D_DIM;
    float s = 0.f;
#pragma unroll
    for (int h = 0; h < 2; h++) {
        int off = h * 128 + lane * 4;
        float4 ev = *reinterpret_cast<const float4*>(er + off);
        float4 zv = *reinterpret_cast<const float4*>(zr + off);
        float dx = ev.x - zv.x, dy = ev.y - zv.y, dz = ev.z - zv.z, dw = ev.w - zv.w;
        s += dx * dx + dy * dy + dz * dz + dw * dw;
        *reinterpret_cast<float4*>(orow + off) = ev;
    }
    if (lane == 0) {
        atomicAdd(&g_counts[bk], 1);
        out_idx_f[token] = (float)bk;
    }
#pragma unroll
    for (int o = 16; o > 0; o >>= 1) s += __shfl_down_sync(0xffffffffu, s, o);
    __shared__ float sh[8];
    __shared__ int last;
    if (lane == 0) sh[warp] = s;
    __syncthreads();
    if (threadIdx.x == 0) {
        float t = 0.f;
        for (int w = 0; w < 8; w++) t += sh[w];
        g_partials[blockIdx.x] = t;
        __threadfence();
        int ticket = atomicAdd(&g_done, 1);
        last = (ticket == gridDim.x - 1) ? 1 : 0;
    }
    __syncthreads();
    if (!last) return;

    __shared__ float red[256];
    const int nPart = gridDim.x;
    float acc = 0.f;
    for (int i = threadIdx.x; i < nPart; i += 256) acc += g_partials[i];
    red[threadIdx.x] = acc;
    __syncthreads();
    for (int st = 128; st > 0; st >>= 1) {
        if (threadIdx.x < st) red[threadIdx.x] += red[threadIdx.x + st];
        __syncthreads();
    }
    float loss = 0.1f * red[0] / (float)((size_t)N * D_DIM);
    __syncthreads();
    float e = 0.f;
    for (int i = threadIdx.x; i < K; i += 256) {
        float p = (float)g_counts[i] / (float)N;
        e += p * logf(p + 1e-10f);
    }
    red[threadIdx.x] = e;
    __syncthreads();
    for (int st = 128; st > 0; st >>= 1) {
        if (threadIdx.x < st) red[threadIdx.x] += red[threadIdx.x + st];
        __syncthreads();
    }
    if (threadIdx.x == 0) {
        out_scalars[0] = loss;
        out_scalars[1] = expf(-red[0]);
        g_done = 0;
    }
}

extern "C" void kernel_launch(void* const* d_in, const int* in_sizes, int n_in,
                              void* d_out, int out_size) {
    const float* Z = (const float*)d_in[0];
    const float* E = (const float*)d_in[1];
    int N = in_sizes[0] / D_DIM;
    int K = in_sizes[1] / D_DIM;

    float* out  = (float*)d_out;
    float* zq   = out;
    float* idxf = out + (size_t)N * D_DIM;
    float* scal = idxf + N;

    cudaFuncSetAttribute(approx_kernel, cudaFuncAttributeMaxDynamicSharedMemorySize, SMEM_TOTAL);

    prep_e_kernel<<<K / 8, 256>>>(E);
    quant_z_kernel<<<N / 8, 256>>>(Z);
    dummy_kernel<<<1, 32>>>();
    approx_kernel<<<N / 128, 256, SMEM_TOTAL>>>();
    rescue_kernel<<<N / 8, 256>>>(Z, E, zq, idxf, scal, N, K);
}

// round 14
// speedup vs baseline: 1.4810x; 1.4810x over previous
#include <cuda_runtime.h>
#include <cuda_fp16.h>
#include <cstdint>

#define D_DIM 256
#define NTOK  65536
#define KCODE 4096

// ---------------- scratch globals ----------------
__device__ float  g_esqp[KCODE];        // esq + 2048 (fp32)
__device__ int    g_counts[KCODE];
__device__ float  g_partials[NTOK / 8];
__device__ __align__(16) __half g_Eh[KCODE * D_DIM];
__device__ __align__(16) uint32_t g_topk[NTOK * 4];
__device__ int    g_done;

// SMEM: A 64KB | B0 16KB | B1 16KB | tops 4KB = 100KB  -> 2 CTAs/SM
#define SM_A    0
#define SM_B0   65536
#define SM_B1   81920
#define SM_TOP  98304
#define SMEM_TOTAL 102400

static __device__ __forceinline__ uint32_t smem_u32(const void* p) {
    uint32_t a;
    asm("{ .reg .u64 t; cvta.to.shared.u64 t, %1; cvt.u32.u64 %0, t; }" : "=r"(a) : "l"(p));
    return a;
}
static __device__ __forceinline__ void ldsm4(uint32_t* r, uint32_t addr) {
    asm volatile("ldmatrix.sync.aligned.m8n8.x4.shared.b16 {%0,%1,%2,%3}, [%4];"
                 : "=r"(r[0]), "=r"(r[1]), "=r"(r[2]), "=r"(r[3]) : "r"(addr));
}
static __device__ __forceinline__ void hmma16816_f16(uint32_t& c0, uint32_t& c1,
                                                     const uint32_t* a, uint32_t b0, uint32_t b1) {
    asm volatile("mma.sync.aligned.m16n8k16.row.col.f16.f16.f16.f16 "
                 "{%0,%1}, {%2,%3,%4,%5}, {%6,%7}, {%0,%1};"
                 : "+r"(c0), "+r"(c1)
                 : "r"(a[0]), "r"(a[1]), "r"(a[2]), "r"(a[3]), "r"(b0), "r"(b1));
}
static __device__ __forceinline__ void cpasync16(uint32_t sa, const void* ga) {
    asm volatile("cp.async.cg.shared.global [%0], [%1], 16;" :: "r"(sa), "l"(ga));
}
static __device__ __forceinline__ void ins4u(uint32_t k, uint32_t& t0, uint32_t& t1,
                                             uint32_t& t2, uint32_t& t3) {
    if (k < t3) {
        uint32_t m2 = min(t2, k);  t3 = max(t2, k);
        uint32_t m1 = min(t1, m2); t2 = max(t1, m2);
        uint32_t m0 = min(t0, m1); t1 = max(t0, m1); t0 = m0;
    }
}

// ---------------- kernel 1: prep E ----------------
__global__ void prep_e_kernel(const float* __restrict__ E) {
    int warp = threadIdx.x >> 5, lane = threadIdx.x & 31;
    int k = blockIdx.x * 8 + warp;
    const float* row = E + (size_t)k * D_DIM;
    float4 a = *reinterpret_cast<const float4*>(row + lane * 8);
    float4 b = *reinterpret_cast<const float4*>(row + lane * 8 + 4);
    float s = a.x * a.x + a.y * a.y + a.z * a.z + a.w * a.w
            + b.x * b.x + b.y * b.y + b.z * b.z + b.w * b.w;
#pragma unroll
    for (int o = 16; o > 0; o >>= 1) s += __shfl_xor_sync(0xffffffffu, s, o);
    __half h[8];
    h[0] = __float2half_rn(a.x); h[1] = __float2half_rn(a.y);
    h[2] = __float2half_rn(a.z); h[3] = __float2half_rn(a.w);
    h[4] = __float2half_rn(b.x); h[5] = __float2half_rn(b.y);
    h[6] = __float2half_rn(b.z); h[7] = __float2half_rn(b.w);
    *reinterpret_cast<uint4*>(g_Eh + (size_t)k * D_DIM + lane * 8) = *reinterpret_cast<uint4*>(h);
    if (lane == 0) g_esqp[k] = s + 2048.0f;
    if (blockIdx.x < 16) g_counts[blockIdx.x * 256 + threadIdx.x] = 0;
}

// ---------------- kernel 2: quarter-pipelined HMMA GEMM + fused top-4 ----------------
// one B quarter: 128 codes x 64 dims (f16) = 128 rows x 128B = 16KB; 1024 chunks / 256 thr
// quarter q of tile nt covers dims [q*64, (q+1)*64)  (q = 0..3)
static __device__ __forceinline__ void load_quarter(uint32_t dst, int nt, int q, int tid) {
    const char* src = (const char*)(g_Eh + (size_t)(nt * 128) * D_DIM + q * 64);
#pragma unroll
    for (int i = 0; i < 4; i++) {
        int c = tid + i * 256;          // 0..1023
        int row = c >> 3, ch = c & 7;   // 128 rows x 8 16B-chunks
        uint32_t sa = dst + row * 128 + (uint32_t)((ch ^ (row & 7)) << 4);
        cpasync16(sa, src + (size_t)row * 512 + ch * 16);
    }
}

__global__ __launch_bounds__(256, 2)
void approx_kernel(const float* __restrict__ Z) {
    extern __shared__ char smem[];
    const uint32_t sb = smem_u32(smem);
    const int tid = threadIdx.x;
    const int lane = tid & 31;
    const int wid = tid >> 5;
    const int wm = wid & 3;      // rows wm*32
    const int wn = wid >> 2;     // cols wn*64
    const int m0 = blockIdx.x * 128;

    // start B pipeline (quarters 0,1 of tile 0)
    load_quarter(sb + SM_B0, 0, 0, tid);
    asm volatile("cp.async.commit_group;" ::: "memory");
    load_quarter(sb + SM_B1, 0, 1, tid);
    asm volatile("cp.async.commit_group;" ::: "memory");

    // fused A conversion: read own fp32 Z rows, write swizzled f16 smem
    {
        int row = tid >> 1, half = tid & 1;
        const float* zr = Z + (size_t)(m0 + row) * D_DIM;
#pragma unroll
        for (int j = 0; j < 16; j++) {
            int ch = half * 16 + j;
            float4 u = *reinterpret_cast<const float4*>(zr + ch * 8);
            float4 w = *reinterpret_cast<const float4*>(zr + ch * 8 + 4);
            __half2 p0 = __floats2half2_rn(u.x, u.y);
            __half2 p1 = __floats2half2_rn(u.z, u.w);
            __half2 p2 = __floats2half2_rn(w.x, w.y);
            __half2 p3 = __floats2half2_rn(w.z, w.w);
            uint4 pk;
            pk.x = *(uint32_t*)&p0; pk.y = *(uint32_t*)&p1;
            pk.z = *(uint32_t*)&p2; pk.w = *(uint32_t*)&p3;
            *reinterpret_cast<uint4*>(smem + SM_A + row * 512 + ((ch ^ (row & 7)) << 4)) = pk;
        }
    }
    __syncthreads();   // A visible to all warps

    uint32_t T[4][4];
#pragma unroll
    for (int s = 0; s < 4; s++) { T[s][0] = T[s][1] = T[s][2] = T[s][3] = 0xFFFFFFFFu; }

    uint32_t acc[2][8][2];

    // 32 tiles x 4 quarters = 128 pipeline steps
#pragma unroll 1
    for (int g = 0; g < 128; g++) {
        const int nt = g >> 2;
        const int q  = g & 3;
        if (q == 0) {
#pragma unroll
            for (int mi = 0; mi < 2; mi++)
#pragma unroll
                for (int nj = 0; nj < 8; nj++) { acc[mi][nj][0] = 0u; acc[mi][nj][1] = 0u; }
        }
        if (g < 126) asm volatile("cp.async.wait_group 1;" ::: "memory");
        else         asm volatile("cp.async.wait_group 0;" ::: "memory");
        __syncthreads();
        const uint32_t Bb = sb + ((g & 1) ? SM_B1 : SM_B0);

        // quarter q covers global k-steps q*4 .. q*4+3 (of 16)
#pragma unroll
        for (int ks = 0; ks < 4; ks++) {
            const int kg = q * 4 + ks;      // global k-step 0..15
            uint32_t a[2][4], b[4][4];
#pragma unroll
            for (int mi = 0; mi < 2; mi++) {
                int ar = wm * 32 + mi * 16 + (lane & 15);
                int ch = kg * 2 + (lane >> 4);        // 16B chunk 0..31 along 512B A row
                ldsm4(a[mi], sb + SM_A + ar * 512 + ((ch ^ (ar & 7)) << 4));
            }
#pragma unroll
            for (int gg = 0; gg < 4; gg++) {
                int br = wn * 64 + gg * 16 + (lane & 7) + ((lane >> 4) & 1) * 8;
                int ch = ks * 2 + ((lane >> 3) & 1);  // 16B chunk 0..7 within quarter row
                ldsm4(b[gg], Bb + br * 128 + ((ch ^ (br & 7)) << 4));
            }
#pragma unroll
            for (int mi = 0; mi < 2; mi++)
#pragma unroll
                for (int gg = 0; gg < 4; gg++) {
                    hmma16816_f16(acc[mi][2 * gg][0],     acc[mi][2 * gg][1],     a[mi], b[gg][0], b[gg][1]);
                    hmma16816_f16(acc[mi][2 * gg + 1][0], acc[mi][2 * gg + 1][1], a[mi], b[gg][2], b[gg][3]);
                }
        }
        __syncthreads();
        if (g + 2 < 128) {
            const int g2 = g + 2;
            load_quarter(sb + ((g & 1) ? SM_B1 : SM_B0), g2 >> 2, g2 & 3, tid);
            asm volatile("cp.async.commit_group;" ::: "memory");
        }

        if (q == 3) {
            // per-tile epilogue (overlapped by the co-resident CTA's MMAs)
            const int kbase = nt * 128 + wn * 64 + (lane & 3) * 2;
#pragma unroll
            for (int nj = 0; nj < 8; nj++) {
                const int kb = kbase + nj * 8;
                float2 e2 = *reinterpret_cast<const float2*>(g_esqp + kb);
#pragma unroll
                for (int mi = 0; mi < 2; mi++)
#pragma unroll
                    for (int h = 0; h < 2; h++) {
                        const int s = mi * 2 + h;
                        float2 d = __half22float2(*reinterpret_cast<__half2*>(&acc[mi][nj][h]));
                        float v0 = fmaf(-2.0f, d.x, e2.x);
                        float v1 = fmaf(-2.0f, d.y, e2.y);
                        uint32_t k0 = (__float_as_uint(v0) & 0xFFFFF000u) | (uint32_t)kb;
                        uint32_t k1 = (__float_as_uint(v1) & 0xFFFFF000u) | (uint32_t)(kb + 1);
                        ins4u(k0, T[s][0], T[s][1], T[s][2], T[s][3]);
                        ins4u(k1, T[s][0], T[s][1], T[s][2], T[s][3]);
                    }
            }
        }
    }

    // quad merge: lanes l^1, l^2 share token rows
#pragma unroll
    for (int off = 1; off <= 2; off <<= 1) {
#pragma unroll
        for (int s = 0; s < 4; s++) {
            uint32_t o0 = __shfl_xor_sync(0xffffffffu, T[s][0], off);
            uint32_t o1 = __shfl_xor_sync(0xffffffffu, T[s][1], off);
            uint32_t o2 = __shfl_xor_sync(0xffffffffu, T[s][2], off);
            uint32_t o3 = __shfl_xor_sync(0xffffffffu, T[s][3], off);
            ins4u(o0, T[s][0], T[s][1], T[s][2], T[s][3]);
            ins4u(o1, T[s][0], T[s][1], T[s][2], T[s][3]);
            ins4u(o2, T[s][0], T[s][1], T[s][2], T[s][3]);
            ins4u(o3, T[s][0], T[s][1], T[s][2], T[s][3]);
        }
    }

    uint32_t* smk = reinterpret_cast<uint32_t*>(smem + SM_TOP);
    if ((lane & 3) == 0) {
#pragma unroll
        for (int s = 0; s < 4; s++) {
            int r = wm * 32 + (s >> 1) * 16 + (s & 1) * 8 + (lane >> 2);
            uint32_t* dst = smk + (r * 2 + wn) * 4;
            dst[0] = T[s][0]; dst[1] = T[s][1]; dst[2] = T[s][2]; dst[3] = T[s][3];
        }
    }
    __syncthreads();
    if (tid < 128) {
        uint4 A4 = *reinterpret_cast<uint4*>(smk + (tid * 2) * 4);
        uint4 B4 = *reinterpret_cast<uint4*>(smk + (tid * 2 + 1) * 4);
        uint32_t a0 = A4.x, a1 = A4.y, a2 = A4.z, a3 = A4.w;
        ins4u(B4.x, a0, a1, a2, a3);
        ins4u(B4.y, a0, a1, a2, a3);
        ins4u(B4.z, a0, a1, a2, a3);
        ins4u(B4.w, a0, a1, a2, a3);
        *reinterpret_cast<uint4*>(&g_topk[(size_t)(m0 + tid) * 4]) = make_uint4(a0, a1, a2, a3);
    }
}

// ---------------- kernel 3: exact rescore + gather + loss + hist + finalize ----------------
__global__ void rescue_kernel(const float* __restrict__ Z, const float* __restrict__ E,
                              float* __restrict__ zq_out, float* __restrict__ out_idx_f,
                              float* __restrict__ out_scalars, int N, int K) {
    const int warp = threadIdx.x >> 5;
    const int lane = threadIdx.x & 31;
    const int token = blockIdx.x * 8 + warp;

    const float* zr = Z + (size_t)token * D_DIM;
    float4 z0 = *reinterpret_cast<const float4*>(zr + lane * 8);
    float4 z1 = *reinterpret_cast<const float4*>(zr + lane * 8 + 4);

    uint4 tk = *reinterpret_cast<const uint4*>(&g_topk[(size_t)token * 4]);
    int ks[4] = { (int)(tk.x & 4095u), (int)(tk.y & 4095u), (int)(tk.z & 4095u), (int)(tk.w & 4095u) };
    float dots[4];
#pragma unroll
    for (int j = 0; j < 4; j++) {
        const float* er = E + (size_t)ks[j] * D_DIM;
        float4 e0 = *reinterpret_cast<const float4*>(er + lane * 8);
        float4 e1 = *reinterpret_cast<const float4*>(er + lane * 8 + 4);
        dots[j] = z0.x * e0.x + z0.y * e0.y + z0.z * e0.z + z0.w * e0.w
                + z1.x * e1.x + z1.y * e1.y + z1.z * e1.z + z1.w * e1.w;
    }
#pragma unroll
    for (int o = 16; o > 0; o >>= 1)
#pragma unroll
        for (int j = 0; j < 4; j++) dots[j] += __shfl_xor_sync(0xffffffffu, dots[j], o);

    float bv = 3.4e38f; int bk = 0x7FFFFFFF;
#pragma unroll
    for (int j = 0; j < 4; j++) {
        float v = g_esqp[ks[j]] - 2048.0f - 2.0f * dots[j];
        if (v < bv || (v == bv && ks[j] < bk)) { bv = v; bk = ks[j]; }
    }

    const float* er = E + (size_t)bk * D_DIM;
    float* orow = zq_out + (size_t)token * D_DIM;
    float s = 0.f;
#pragma unroll
    for (int h = 0; h < 2; h++) {
        int off = h * 128 + lane * 4;
        float4 ev = *reinterpret_cast<const float4*>(er + off);
        float4 zv = *reinterpret_cast<const float4*>(zr + off);
        float dx = ev.x - zv.x, dy = ev.y - zv.y, dz = ev.z - zv.z, dw = ev.w - zv.w;
        s += dx * dx + dy * dy + dz * dz + dw * dw;
        *reinterpret_cast<float4*>(orow + off) = ev;
    }
    if (lane == 0) {
        atomicAdd(&g_counts[bk], 1);
        out_idx_f[token] = (float)bk;
    }
#pragma unroll
    for (int o = 16; o > 0; o >>= 1) s += __shfl_down_sync(0xffffffffu, s, o);
    __shared__ float sh[8];
    __shared__ int last;
    if (lane == 0) sh[warp] = s;
    __syncthreads();
    if (threadIdx.x == 0) {
        float t = 0.f;
        for (int w = 0; w < 8; w++) t += sh[w];
        g_partials[blockIdx.x] = t;
        __threadfence();
        int ticket = atomicAdd(&g_done, 1);
        last = (ticket == gridDim.x - 1) ? 1 : 0;
    }
    __syncthreads();
    if (!last) return;

    __shared__ float red[256];
    const int nPart = gridDim.x;
    float acc = 0.f;
    for (int i = threadIdx.x; i < nPart; i += 256) acc += g_partials[i];
    red[threadIdx.x] = acc;
    __syncthreads();
    for (int st = 128; st > 0; st >>= 1) {
        if (threadIdx.x < st) red[threadIdx.x] += red[threadIdx.x + st];
        __syncthreads();
    }
    float loss = 0.1f * red[0] / (float)((size_t)N * D_DIM);
    __syncthreads();
    float e = 0.f;
    for (int i = threadIdx.x; i < K; i += 256) {
        float p = (float)g_counts[i] / (float)N;
        e += p * logf(p + 1e-10f);
    }
    red[threadIdx.x] = e;
    __syncthreads();
    for (int st = 128; st > 0; st >>= 1) {
        if (threadIdx.x < st) red[threadIdx.x] += red[threadIdx.x + st];
        __syncthreads();
    }
    if (threadIdx.x == 0) {
        out_scalars[0] = loss;
        out_scalars[1] = expf(-red[0]);
        g_done = 0;
    }
}

extern "C" void kernel_launch(void* const* d_in, const int* in_sizes, int n_in,
                              void* d_out, int out_size) {
    const float* Z = (const float*)d_in[0];
    const float* E = (const float*)d_in[1];
    int N = in_sizes[0] / D_DIM;
    int K = in_sizes[1] / D_DIM;

    float* out  = (float*)d_out;
    float* zq   = out;
    float* idxf = out + (size_t)N * D_DIM;
    float* scal = idxf + N;

    cudaFuncSetAttribute(approx_kernel, cudaFuncAttributeMaxDynamicSharedMemorySize, SMEM_TOTAL);

    prep_e_kernel<<<K / 8, 256>>>(E);
    approx_kernel<<<N / 128, 256, SMEM_TOTAL>>>(Z);
    rescue_kernel<<<N / 8, 256>>>(Z, E, zq, idxf, scal, N, K);
}

// round 15
// speedup vs baseline: 1.7118x; 1.1558x over previous
#include <cuda_runtime.h>
#include <cuda_fp16.h>
#include <cstdint>

#define D_DIM 256
#define NTOK  65536
#define KCODE 4096
#define NT_HALF 16    // tiles per CTA (half of E)

// ---------------- scratch globals ----------------
__device__ float  g_esqp[KCODE];        // esq + 2048 (fp32)
__device__ int    g_counts[KCODE];
__device__ float  g_partials[NTOK / 8];
__device__ __align__(16) __half g_Eh[KCODE * D_DIM];
__device__ __align__(16) __half g_Zh[NTOK * D_DIM];
__device__ __align__(16) uint32_t g_topk[NTOK * 8];
__device__ int    g_done;

// SMEM: A 64KB | B0 64KB | B1 64KB | tops 4KB
#define SM_A    0
#define SM_B0   65536
#define SM_B1   131072
#define SM_TOP  196608
#define SMEM_TOTAL 200704

static __device__ __forceinline__ uint32_t smem_u32(const void* p) {
    uint32_t a;
    asm("{ .reg .u64 t; cvta.to.shared.u64 t, %1; cvt.u32.u64 %0, t; }" : "=r"(a) : "l"(p));
    return a;
}
static __device__ __forceinline__ void ldsm4(uint32_t* r, uint32_t addr) {
    asm volatile("ldmatrix.sync.aligned.m8n8.x4.shared.b16 {%0,%1,%2,%3}, [%4];"
                 : "=r"(r[0]), "=r"(r[1]), "=r"(r[2]), "=r"(r[3]) : "r"(addr));
}
static __device__ __forceinline__ void hmma16816_f16(uint32_t& c0, uint32_t& c1,
                                                     const uint32_t* a, uint32_t b0, uint32_t b1) {
    asm volatile("mma.sync.aligned.m16n8k16.row.col.f16.f16.f16.f16 "
                 "{%0,%1}, {%2,%3,%4,%5}, {%6,%7}, {%0,%1};"
                 : "+r"(c0), "+r"(c1)
                 : "r"(a[0]), "r"(a[1]), "r"(a[2]), "r"(a[3]), "r"(b0), "r"(b1));
}
static __device__ __forceinline__ void cpasync16(uint32_t sa, const void* ga) {
    asm volatile("cp.async.cg.shared.global [%0], [%1], 16;" :: "r"(sa), "l"(ga));
}
static __device__ __forceinline__ void ins4u(uint32_t k, uint32_t& t0, uint32_t& t1,
                                             uint32_t& t2, uint32_t& t3) {
    if (k < t3) {
        uint32_t m2 = min(t2, k);  t3 = max(t2, k);
        uint32_t m1 = min(t1, m2); t2 = max(t1, m2);
        uint32_t m0 = min(t0, m1); t1 = max(t0, m1); t0 = m0;
    }
}

// ---------------- kernel 1: prep E ----------------
__global__ void prep_e_kernel(const float* __restrict__ E) {
    int warp = threadIdx.x >> 5, lane = threadIdx.x & 31;
    int k = blockIdx.x * 8 + warp;
    const float* row = E + (size_t)k * D_DIM;
    float4 a = *reinterpret_cast<const float4*>(row + lane * 8);
    float4 b = *reinterpret_cast<const float4*>(row + lane * 8 + 4);
    float s = a.x * a.x + a.y * a.y + a.z * a.z + a.w * a.w
            + b.x * b.x + b.y * b.y + b.z * b.z + b.w * b.w;
#pragma unroll
    for (int o = 16; o > 0; o >>= 1) s += __shfl_xor_sync(0xffffffffu, s, o);
    __half h[8];
    h[0] = __float2half_rn(a.x); h[1] = __float2half_rn(a.y);
    h[2] = __float2half_rn(a.z); h[3] = __float2half_rn(a.w);
    h[4] = __float2half_rn(b.x); h[5] = __float2half_rn(b.y);
    h[6] = __float2half_rn(b.z); h[7] = __float2half_rn(b.w);
    *reinterpret_cast<uint4*>(g_Eh + (size_t)k * D_DIM + lane * 8) = *reinterpret_cast<uint4*>(h);
    if (lane == 0) g_esqp[k] = s + 2048.0f;
    if (blockIdx.x < 16) g_counts[blockIdx.x * 256 + threadIdx.x] = 0;
}

// ---------------- kernel 2: Z -> fp16 ----------------
__global__ void quant_z_kernel(const float* __restrict__ Z) {
    int warp = threadIdx.x >> 5, lane = threadIdx.x & 31;
    int n = blockIdx.x * 8 + warp;
    const float* row = Z + (size_t)n * D_DIM;
    float4 a = *reinterpret_cast<const float4*>(row + lane * 8);
    float4 b = *reinterpret_cast<const float4*>(row + lane * 8 + 4);
    __half h[8];
    h[0] = __float2half_rn(a.x); h[1] = __float2half_rn(a.y);
    h[2] = __float2half_rn(a.z); h[3] = __float2half_rn(a.w);
    h[4] = __float2half_rn(b.x); h[5] = __float2half_rn(b.y);
    h[6] = __float2half_rn(b.z); h[7] = __float2half_rn(b.w);
    *reinterpret_cast<uint4*>(g_Zh + (size_t)n * D_DIM + lane * 8) = *reinterpret_cast<uint4*>(h);
}

__global__ void dummy_kernel() {}

// ---------------- kernel 3: N-split HMMA GEMM + interleaved top-4 ----------------
static __device__ __forceinline__ void load_tile_f16(uint32_t dst, const __half* gsrc, int tid) {
    const char* gbase = (const char*)gsrc;
#pragma unroll
    for (int i = 0; i < 16; i++) {
        int c = tid + i * 256;
        int row = c >> 5, ch = c & 31;
        uint32_t sa = dst + row * 512 + (uint32_t)((ch ^ (row & 7)) << 4);
        cpasync16(sa, gbase + row * 512 + ch * 16);
    }
}

// one tile: MMAs into cur[], interleaved epilogue of prev[] (tile nt-1)
static __device__ __forceinline__ void tile_body(
    int nt, bool hasPrev, int n0base, uint32_t sb, int tid, int lane, int wm, int wn,
    uint32_t cur[2][8][2], uint32_t prev[2][8][2], uint32_t T[4][4])
{
    if (nt < NT_HALF - 1) asm volatile("cp.async.wait_group 1;" ::: "memory");
    else                  asm volatile("cp.async.wait_group 0;" ::: "memory");
    __syncthreads();
    const uint32_t Bb = sb + ((nt & 1) ? SM_B1 : SM_B0);

    float2 e2[8];
    const int kbase = n0base + (nt - 1) * 128 + wn * 64 + (lane & 3) * 2;
    if (hasPrev) {
#pragma unroll
        for (int nj = 0; nj < 8; nj++)
            e2[nj] = *reinterpret_cast<const float2*>(g_esqp + kbase + nj * 8);
    }

#pragma unroll
    for (int mi = 0; mi < 2; mi++)
#pragma unroll
        for (int nj = 0; nj < 8; nj++) { cur[mi][nj][0] = 0u; cur[mi][nj][1] = 0u; }

#pragma unroll
    for (int ks = 0; ks < 16; ks++) {
        uint32_t a[2][4], b[4][4];
#pragma unroll
        for (int mi = 0; mi < 2; mi++) {
            int ar = wm * 32 + mi * 16 + (lane & 15);
            int ch = ks * 2 + (lane >> 4);
            ldsm4(a[mi], sb + SM_A + ar * 512 + ((ch ^ (ar & 7)) << 4));
        }
#pragma unroll
        for (int g = 0; g < 4; g++) {
            int br = wn * 64 + g * 16 + (lane & 7) + ((lane >> 4) & 1) * 8;
            int ch = ks * 2 + ((lane >> 3) & 1);
            ldsm4(b[g], Bb + br * 512 + ((ch ^ (br & 7)) << 4));
        }
#pragma unroll
        for (int mi = 0; mi < 2; mi++)
#pragma unroll
            for (int g = 0; g < 4; g++) {
                hmma16816_f16(cur[mi][2 * g][0],     cur[mi][2 * g][1],     a[mi], b[g][0], b[g][1]);
                hmma16816_f16(cur[mi][2 * g + 1][0], cur[mi][2 * g + 1][1], a[mi], b[g][2], b[g][3]);
            }

        // interleaved epilogue chunk of tile nt-1
        if (hasPrev) {
            const int nj = ks >> 1;
            const int mi = ks & 1;
            const int kb = kbase + nj * 8;
#pragma unroll
            for (int h = 0; h < 2; h++) {
                const int s = mi * 2 + h;
                float2 d = __half22float2(*reinterpret_cast<__half2*>(&prev[mi][nj][h]));
                float v0 = fmaf(-2.0f, d.x, e2[nj].x);
                float v1 = fmaf(-2.0f, d.y, e2[nj].y);
                uint32_t k0 = (__float_as_uint(v0) & 0xFFFFF000u) | (uint32_t)kb;
                uint32_t k1 = (__float_as_uint(v1) & 0xFFFFF000u) | (uint32_t)(kb + 1);
                ins4u(k0, T[s][0], T[s][1], T[s][2], T[s][3]);
                ins4u(k1, T[s][0], T[s][1], T[s][2], T[s][3]);
            }
        }
    }
    __syncthreads();
    if (nt + 2 < NT_HALF) {
        load_tile_f16(sb + ((nt & 1) ? SM_B1 : SM_B0),
                      g_Eh + (size_t)(n0base + (nt + 2) * 128) * D_DIM, tid);
        asm volatile("cp.async.commit_group;" ::: "memory");
    }
}

static __device__ __forceinline__ void tail_epilogue(
    int n0base, int lane, int wn, uint32_t prev[2][8][2], uint32_t T[4][4])
{
    const int kbase = n0base + (NT_HALF - 1) * 128 + wn * 64 + (lane & 3) * 2;
#pragma unroll
    for (int nj = 0; nj < 8; nj++) {
        const int kb = kbase + nj * 8;
        float2 e2 = *reinterpret_cast<const float2*>(g_esqp + kb);
#pragma unroll
        for (int mi = 0; mi < 2; mi++)
#pragma unroll
            for (int h = 0; h < 2; h++) {
                const int s = mi * 2 + h;
                float2 d = __half22float2(*reinterpret_cast<__half2*>(&prev[mi][nj][h]));
                float v0 = fmaf(-2.0f, d.x, e2.x);
                float v1 = fmaf(-2.0f, d.y, e2.y);
                uint32_t k0 = (__float_as_uint(v0) & 0xFFFFF000u) | (uint32_t)kb;
                uint32_t k1 = (__float_as_uint(v1) & 0xFFFFF000u) | (uint32_t)(kb + 1);
                ins4u(k0, T[s][0], T[s][1], T[s][2], T[s][3]);
                ins4u(k1, T[s][0], T[s][1], T[s][2], T[s][3]);
            }
    }
}

__global__ __launch_bounds__(256, 1)
void approx_kernel() {
    extern __shared__ char smem[];
    const uint32_t sb = smem_u32(smem);
    const int tid = threadIdx.x;
    const int lane = tid & 31;
    const int wid = tid >> 5;
    const int wm = wid & 3;
    const int wn = wid >> 2;
    const int m0 = (blockIdx.x >> 1) * 128;     // token tile
    const int half = blockIdx.x & 1;            // E half
    const int n0base = half * (NT_HALF * 128);  // 0 or 2048

    load_tile_f16(sb + SM_A, g_Zh + (size_t)m0 * D_DIM, tid);
    load_tile_f16(sb + SM_B0, g_Eh + (size_t)n0base * D_DIM, tid);
    asm volatile("cp.async.commit_group;" ::: "memory");
    load_tile_f16(sb + SM_B1, g_Eh + (size_t)(n0base + 128) * D_DIM, tid);
    asm volatile("cp.async.commit_group;" ::: "memory");

    uint32_t T[4][4];
#pragma unroll
    for (int s = 0; s < 4; s++) { T[s][0] = T[s][1] = T[s][2] = T[s][3] = 0xFFFFFFFFu; }

    uint32_t accA[2][8][2], accB[2][8][2];

#pragma unroll 1
    for (int p = 0; p < NT_HALF / 2; p++) {
        tile_body(2 * p,     (p > 0), n0base, sb, tid, lane, wm, wn, accA, accB, T);
        tile_body(2 * p + 1, true,    n0base, sb, tid, lane, wm, wn, accB, accA, T);
    }
    tail_epilogue(n0base, lane, wn, accB, T);

    // quad merge: lanes l^1, l^2 share token rows
#pragma unroll
    for (int off = 1; off <= 2; off <<= 1) {
#pragma unroll
        for (int s = 0; s < 4; s++) {
            uint32_t o0 = __shfl_xor_sync(0xffffffffu, T[s][0], off);
            uint32_t o1 = __shfl_xor_sync(0xffffffffu, T[s][1], off);
            uint32_t o2 = __shfl_xor_sync(0xffffffffu, T[s][2], off);
            uint32_t o3 = __shfl_xor_sync(0xffffffffu, T[s][3], off);
            ins4u(o0, T[s][0], T[s][1], T[s][2], T[s][3]);
            ins4u(o1, T[s][0], T[s][1], T[s][2], T[s][3]);
            ins4u(o2, T[s][0], T[s][1], T[s][2], T[s][3]);
            ins4u(o3, T[s][0], T[s][1], T[s][2], T[s][3]);
        }
    }

    uint32_t* smk = reinterpret_cast<uint32_t*>(smem + SM_TOP);
    if ((lane & 3) == 0) {
#pragma unroll
        for (int s = 0; s < 4; s++) {
            int r = wm * 32 + (s >> 1) * 16 + (s & 1) * 8 + (lane >> 2);
            uint32_t* dst = smk + (r * 2 + wn) * 4;
            dst[0] = T[s][0]; dst[1] = T[s][1]; dst[2] = T[s][2]; dst[3] = T[s][3];
        }
    }
    __syncthreads();
    if (tid < 128) {
        uint4 A4 = *reinterpret_cast<uint4*>(smk + (tid * 2) * 4);
        uint4 B4 = *reinterpret_cast<uint4*>(smk + (tid * 2 + 1) * 4);
        uint32_t a0 = A4.x, a1 = A4.y, a2 = A4.z, a3 = A4.w;
        ins4u(B4.x, a0, a1, a2, a3);
        ins4u(B4.y, a0, a1, a2, a3);
        ins4u(B4.z, a0, a1, a2, a3);
        ins4u(B4.w, a0, a1, a2, a3);
        *reinterpret_cast<uint4*>(&g_topk[(size_t)(m0 + tid) * 8 + half * 4]) =
            make_uint4(a0, a1, a2, a3);
    }
}

// ---------------- kernel 4: merge halves + exact rescore + gather + loss + hist + finalize ----------------
__global__ void rescue_kernel(const float* __restrict__ Z, const float* __restrict__ E,
                              float* __restrict__ zq_out, float* __restrict__ out_idx_f,
                              float* __restrict__ out_scalars, int N, int K) {
    const int warp = threadIdx.x >> 5;
    const int lane = threadIdx.x & 31;
    const int token = blockIdx.x * 8 + warp;

    const float* zr = Z + (size_t)token * D_DIM;
    float4 z0 = *reinterpret_cast<const float4*>(zr + lane * 8);
    float4 z1 = *reinterpret_cast<const float4*>(zr + lane * 8 + 4);

    // merge the two sorted half-lists by key -> global top-4
    uint4 tkA = *reinterpret_cast<const uint4*>(&g_topk[(size_t)token * 8]);
    uint4 tkB = *reinterpret_cast<const uint4*>(&g_topk[(size_t)token * 8 + 4]);
    uint32_t a0 = tkA.x, a1 = tkA.y, a2 = tkA.z, a3 = tkA.w;
    ins4u(tkB.x, a0, a1, a2, a3);
    ins4u(tkB.y, a0, a1, a2, a3);
    ins4u(tkB.z, a0, a1, a2, a3);
    ins4u(tkB.w, a0, a1, a2, a3);

    int ks[4] = { (int)(a0 & 4095u), (int)(a1 & 4095u), (int)(a2 & 4095u), (int)(a3 & 4095u) };
    float dots[4];
#pragma unroll
    for (int j = 0; j < 4; j++) {
        const float* er = E + (size_t)ks[j] * D_DIM;
        float4 e0 = *reinterpret_cast<const float4*>(er + lane * 8);
        float4 e1 = *reinterpret_cast<const float4*>(er + lane * 8 + 4);
        dots[j] = z0.x * e0.x + z0.y * e0.y + z0.z * e0.z + z0.w * e0.w
                + z1.x * e1.x + z1.y * e1.y + z1.z * e1.z + z1.w * e1.w;
    }
#pragma unroll
    for (int o = 16; o > 0; o >>= 1)
#pragma unroll
        for (int j = 0; j < 4; j++) dots[j] += __shfl_xor_sync(0xffffffffu, dots[j], o);

    float bv = 3.4e38f; int bk = 0x7FFFFFFF;
#pragma unroll
    for (int j = 0; j < 4; j++) {
        float v = g_esqp[ks[j]] - 2048.0f - 2.0f * dots[j];
        if (v < bv || (v == bv && ks[j] < bk)) { bv = v; bk = ks[j]; }
    }

    const float* er = E + (size_t)bk * D_DIM;
    float* orow = zq_out + (size_t)token * D_DIM;
    float s = 0.f;
#pragma unroll
    for (int h = 0; h < 2; h++) {
        int off = h * 128 + lane * 4;
        float4 ev = *reinterpret_cast<const float4*>(er + off);
        float4 zv = *reinterpret_cast<const float4*>(zr + off);
        float dx = ev.x - zv.x, dy = ev.y - zv.y, dz = ev.z - zv.z, dw = ev.w - zv.w;
        s += dx * dx + dy * dy + dz * dz + dw * dw;
        *reinterpret_cast<float4*>(orow + off) = ev;
    }
    if (lane == 0) {
        atomicAdd(&g_counts[bk], 1);
        out_idx_f[token] = (float)bk;
    }
#pragma unroll
    for (int o = 16; o > 0; o >>= 1) s += __shfl_down_sync(0xffffffffu, s, o);
    __shared__ float sh[8];
    __shared__ int last;
    if (lane == 0) sh[warp] = s;
    __syncthreads();
    if (threadIdx.x == 0) {
        float t = 0.f;
        for (int w = 0; w < 8; w++) t += sh[w];
        g_partials[blockIdx.x] = t;
        __threadfence();
        int ticket = atomicAdd(&g_done, 1);
        last = (ticket == gridDim.x - 1) ? 1 : 0;
    }
    __syncthreads();
    if (!last) return;

    __shared__ float red[256];
    const int nPart = gridDim.x;
    float acc = 0.f;
    for (int i = threadIdx.x; i < nPart; i += 256) acc += g_partials[i];
    red[threadIdx.x] = acc;
    __syncthreads();
    for (int st = 128; st > 0; st >>= 1) {
        if (threadIdx.x < st) red[threadIdx.x] += red[threadIdx.x + st];
        __syncthreads();
    }
    float loss = 0.1f * red[0] / (float)((size_t)N * D_DIM);
    __syncthreads();
    float e = 0.f;
    for (int i = threadIdx.x; i < K; i += 256) {
        float p = (float)g_counts[i] / (float)N;
        e += p * logf(p + 1e-10f);
    }
    red[threadIdx.x] = e;
    __syncthreads();
    for (int st = 128; st > 0; st >>= 1) {
        if (threadIdx.x < st) red[threadIdx.x] += red[threadIdx.x + st];
        __syncthreads();
    }
    if (threadIdx.x == 0) {
        out_scalars[0] = loss;
        out_scalars[1] = expf(-red[0]);
        g_done = 0;
    }
}

extern "C" void kernel_launch(void* const* d_in, const int* in_sizes, int n_in,
                              void* d_out, int out_size) {
    const float* Z = (const float*)d_in[0];
    const float* E = (const float*)d_in[1];
    int N = in_sizes[0] / D_DIM;
    int K = in_sizes[1] / D_DIM;

    float* out  = (float*)d_out;
    float* zq   = out;
    float* idxf = out + (size_t)N * D_DIM;
    float* scal = idxf + N;

    cudaFuncSetAttribute(approx_kernel, cudaFuncAttributeMaxDynamicSharedMemorySize, SMEM_TOTAL);

    prep_e_kernel<<<K / 8, 256>>>(E);
    quant_z_kernel<<<N / 8, 256>>>(Z);
    dummy_kernel<<<1, 32>>>();
    approx_kernel<<<(N / 128) * 2, 256, SMEM_TOTAL>>>();
    rescue_kernel<<<N / 8, 256>>>(Z, E, zq, idxf, scal, N, K);
}